// round 15
// baseline (speedup 1.0000x reference)
#include <cuda_runtime.h>

// ---------------- problem constants ----------------
#define Bsz 256
#define Nn  2304
#define Cc  10
#define Dd  16
#define Oo  160          // Cc*Dd
#define Ii  8

#define K1_BT 32                 // batches per GEMM block
#define K1_NC 16                 // n per GEMM block
#define K1_CH (Nn / K1_NC)       // 144 chunks
#define K1_ST 4                  // n per W smem stage
#define K2_NC 24                 // n per routing warp
#define K2_CH (Nn / K2_NC)       // 96 chunks
#define PSTR  K1_CH              // partial-buffer chunk stride (max of 144,96)

// ---------------- scratch (static device globals; no runtime alloc) ----------
__device__ float g_uhat[(size_t)Bsz * Nn * Oo];      // 377 MB fp32
__device__ float g_P[(size_t)Bsz * PSTR * Oo];       // partial s sums
__device__ float g_s0[Bsz * Oo];
__device__ float g_s01[Bsz * Oo];

// ============ K1: 32 b / 16 n per block; vectorized LDS; W via smem =========
// 160 threads: oq = tid%40 (o-quad), grp = tid/40 -> 8 b's of 32.
// __launch_bounds__(160,3) caps regs at 136 -> 3 blocks/SM.
__global__ __launch_bounds__(160, 3) void k1_gemm(const float* __restrict__ x,
                                                  const float* __restrict__ W)
{
    __shared__ float  xs[K1_BT][K1_NC][Ii];          // 16 KB
    __shared__ float4 sW[K1_ST][Ii][Oo / 4];         // 20 KB
    const int b0    = blockIdx.x * K1_BT;
    const int n0    = blockIdx.y * K1_NC;
    const int chunk = blockIdx.y;
    const int tid   = threadIdx.x;
    const int oq    = tid % 40;                      // o = 4*oq .. 4*oq+3
    const int grp   = tid / 40;                      // 0..3 -> 8-b subgroup

    // cooperative load of x tile: [32 b][16 n][8 i] = 1024 float4
    {
        const float4* xsrc = (const float4*)x;
        for (int idx = tid; idx < K1_BT * K1_NC * Ii / 4; idx += 160) {
            int bb = idx >> 5;                       // 32 float4 per b
            int j  = idx & 31;
            ((float4*)xs)[idx] =
                xsrc[(((size_t)(b0 + bb) * Nn + n0) * Ii >> 2) + j];
        }
    }
    __syncthreads();

    float4 acc[8];
#pragma unroll
    for (int bb = 0; bb < 8; bb++) acc[bb] = make_float4(0.f, 0.f, 0.f, 0.f);

    for (int st = 0; st < K1_NC / K1_ST; st++) {
        // stage W[n0+4st .. +3]: 5120 contiguous floats = 1280 float4
        __syncthreads();                              // prev-stage reads done
        const float4* wsrc =
            (const float4*)(W + (size_t)(n0 + st * K1_ST) * Ii * Oo);
#pragma unroll
        for (int k = 0; k < (K1_ST * Ii * Oo / 4) / 160; k++)
            ((float4*)sW)[tid + k * 160] = wsrc[tid + k * 160];
        __syncthreads();

#pragma unroll
        for (int nn2 = 0; nn2 < K1_ST; nn2++) {
            const int nn = st * K1_ST + nn2;
            const int n  = n0 + nn;
            float4 w4[Ii];
#pragma unroll
            for (int i = 0; i < Ii; i++) w4[i] = sW[nn2][i][oq];   // LDS.128
#pragma unroll
            for (int bb = 0; bb < 8; bb++) {
                const int bloc = grp * 8 + bb;
                const float4 xa = *(const float4*)&xs[bloc][nn][0]; // LDS.128 bcast
                const float4 xb = *(const float4*)&xs[bloc][nn][4]; // LDS.128 bcast
                float4 u = make_float4(0.f, 0.f, 0.f, 0.f);
                u.x = fmaf(xa.x, w4[0].x, u.x); u.y = fmaf(xa.x, w4[0].y, u.y);
                u.z = fmaf(xa.x, w4[0].z, u.z); u.w = fmaf(xa.x, w4[0].w, u.w);
                u.x = fmaf(xa.y, w4[1].x, u.x); u.y = fmaf(xa.y, w4[1].y, u.y);
                u.z = fmaf(xa.y, w4[1].z, u.z); u.w = fmaf(xa.y, w4[1].w, u.w);
                u.x = fmaf(xa.z, w4[2].x, u.x); u.y = fmaf(xa.z, w4[2].y, u.y);
                u.z = fmaf(xa.z, w4[2].z, u.z); u.w = fmaf(xa.z, w4[2].w, u.w);
                u.x = fmaf(xa.w, w4[3].x, u.x); u.y = fmaf(xa.w, w4[3].y, u.y);
                u.z = fmaf(xa.w, w4[3].z, u.z); u.w = fmaf(xa.w, w4[3].w, u.w);
                u.x = fmaf(xb.x, w4[4].x, u.x); u.y = fmaf(xb.x, w4[4].y, u.y);
                u.z = fmaf(xb.x, w4[4].z, u.z); u.w = fmaf(xb.x, w4[4].w, u.w);
                u.x = fmaf(xb.y, w4[5].x, u.x); u.y = fmaf(xb.y, w4[5].y, u.y);
                u.z = fmaf(xb.y, w4[5].z, u.z); u.w = fmaf(xb.y, w4[5].w, u.w);
                u.x = fmaf(xb.z, w4[6].x, u.x); u.y = fmaf(xb.z, w4[6].y, u.y);
                u.z = fmaf(xb.z, w4[6].z, u.z); u.w = fmaf(xb.z, w4[6].w, u.w);
                u.x = fmaf(xb.w, w4[7].x, u.x); u.y = fmaf(xb.w, w4[7].y, u.y);
                u.z = fmaf(xb.w, w4[7].z, u.z); u.w = fmaf(xb.w, w4[7].w, u.w);
                *(float4*)&g_uhat[(size_t)((b0 + bloc) * Nn + n) * Oo + oq * 4] = u;
                acc[bb].x += u.x;  acc[bb].y += u.y;
                acc[bb].z += u.z;  acc[bb].w += u.w;   // fixed n-order fp32
            }
        }
    }
#pragma unroll
    for (int bb = 0; bb < 8; bb++) {
        const int bloc = grp * 8 + bb;
        *(float4*)&g_P[(size_t)((b0 + bloc) * PSTR + chunk) * Oo + oq * 4] = acc[bb];
    }
}

// ============ R0: s0 = 0.1 * sum_n u_hat + 0.1 ===============================
__global__ void k_r0(void)
{
    int idx = blockIdx.x * blockDim.x + threadIdx.x;
    if (idx >= Bsz * Oo) return;
    int b = idx / Oo, o = idx - b * Oo;
    float s = 0.f;
#pragma unroll 8
    for (int ch = 0; ch < K1_CH; ch++)
        s += g_P[(size_t)(b * PSTR + ch) * Oo + o];
    g_s0[idx] = 0.1f * s + 0.1f;
}

// ============ routing pass: logits -> softmax -> weighted partial sums =======
__global__ __launch_bounds__(256) void k_route(int use_s01)
{
    const int lane = threadIdx.x & 31;
    const int warp = threadIdx.x >> 5;
    const int ch   = (blockIdx.x << 3) + warp;     // 0..95
    const int b    = blockIdx.y;                   // 0..255
    const int n0   = ch * K2_NC;
    const bool j2v = (lane < 16);

    const float2* sv = (const float2*)((use_s01 ? g_s01 : g_s0) + b * Oo);
    float2 sr0 = sv[lane];
    float2 sr1 = sv[lane + 32];
    float2 sr2 = make_float2(0.f, 0.f);
    if (j2v) sr2 = sv[lane + 64];

    float2 a0 = make_float2(0.f, 0.f);
    float2 a1 = make_float2(0.f, 0.f);
    float2 a2 = make_float2(0.f, 0.f);

    const float2* up = (const float2*)g_uhat
                       + ((size_t)(b * Nn + n0) * Oo >> 1) + lane;

    float2 u0 = up[0];
    float2 u1 = up[32];
    float2 u2 = make_float2(0.f, 0.f);
    if (j2v) u2 = up[64];

#pragma unroll 2
    for (int nn = 0; nn < K2_NC; nn++) {
        float2 t0, t1, t2 = make_float2(0.f, 0.f);
        if (nn + 1 < K2_NC) {
            const float2* upn = up + (Oo >> 1);
            t0 = upn[0];
            t1 = upn[32];
            if (j2v) t2 = upn[64];
        } else {
            t0 = make_float2(0.f, 0.f);
            t1 = make_float2(0.f, 0.f);
        }
        up += (Oo >> 1);

        float p0 = fmaf(u0.y, sr0.y, u0.x * sr0.x);
        float p1 = fmaf(u1.y, sr1.y, u1.x * sr1.x);
        float p2 = fmaf(u2.y, sr2.y, u2.x * sr2.x);
#pragma unroll
        for (int off = 1; off <= 4; off <<= 1) {
            p0 += __shfl_xor_sync(0xffffffffu, p0, off);
            p1 += __shfl_xor_sync(0xffffffffu, p1, off);
            p2 += __shfl_xor_sync(0xffffffffu, p2, off);
        }
        if (!j2v) p2 = -1e30f;

        float m = fmaxf(fmaxf(p0, p1), p2);
        m = fmaxf(m, __shfl_xor_sync(0xffffffffu, m, 8));
        m = fmaxf(m, __shfl_xor_sync(0xffffffffu, m, 16));

        float e0 = __expf(p0 - m);
        float e1 = __expf(p1 - m);
        float e2 = __expf(p2 - m);
        float s  = e0 + e1 + e2;
        s += __shfl_xor_sync(0xffffffffu, s, 8);
        s += __shfl_xor_sync(0xffffffffu, s, 16);
        float inv = __fdividef(1.f, s);

        float w0 = e0 * inv, w1 = e1 * inv, w2 = e2 * inv;
        a0.x = fmaf(w0, u0.x, a0.x);  a0.y = fmaf(w0, u0.y, a0.y);
        a1.x = fmaf(w1, u1.x, a1.x);  a1.y = fmaf(w1, u1.y, a1.y);
        a2.x = fmaf(w2, u2.x, a2.x);  a2.y = fmaf(w2, u2.y, a2.y);

        u0 = t0; u1 = t1; u2 = t2;
    }

    float2* P = (float2*)(g_P + (size_t)(b * PSTR + ch) * Oo);
    P[lane]      = a0;
    P[lane + 32] = a1;
    if (j2v) P[lane + 64] = a2;
}

// ============ R1: s1 = sum + 0.1 ; s01 = s0 + s1 =============================
__global__ void k_r1(void)
{
    int idx = blockIdx.x * blockDim.x + threadIdx.x;
    if (idx >= Bsz * Oo) return;
    int b = idx / Oo, o = idx - b * Oo;
    float s = 0.f;
#pragma unroll 8
    for (int ch = 0; ch < K2_CH; ch++)
        s += g_P[(size_t)(b * PSTR + ch) * Oo + o];
    g_s01[idx] = g_s0[idx] + (s + 0.1f);
}

// ============ R2: s2 = sum + 0.1 ; v = squash(s2) ============================
__global__ __launch_bounds__(256) void k_r2_squash(float* __restrict__ out)
{
    const int wg   = (blockIdx.x << 3) + (threadIdx.x >> 5);   // 2560 warps
    const int lane = threadIdx.x & 31;
    const int b = wg / Cc;
    const int c = wg - b * Cc;
    float s = 0.f;
    if (lane < Dd) {
#pragma unroll 8
        for (int ch = 0; ch < K2_CH; ch++)
            s += g_P[(size_t)(b * PSTR + ch) * Oo + c * Dd + lane];
        s += 0.1f;
    }
    float t = s * s;
#pragma unroll
    for (int off = 8; off >= 1; off >>= 1)
        t += __shfl_xor_sync(0xffffffffu, t, off);
    float nrm = sqrtf(t);
    if (lane < Dd)
        out[(b * Cc + c) * Dd + lane] = s * nrm / (1.0f + t);
}

// ============ launch =========================================================
extern "C" void kernel_launch(void* const* d_in, const int* in_sizes, int n_in,
                              void* d_out, int out_size)
{
    const float* x = (const float*)d_in[0];   // [256,2304,8]
    const float* W = (const float*)d_in[1];   // [2304,8,160]
    float* out = (float*)d_out;               // [256,10,16]

    dim3 g1(Bsz / K1_BT, K1_CH);              // 8 x 144
    dim3 gr(K2_CH / 8, Bsz);                  // 12 x 256 = 3072 blocks

    k1_gemm<<<g1, 160>>>(x, W);
    k_r0<<<160, 256>>>();
    k_route<<<gr, 256>>>(0);                  // pass 2 (s0 -> c1 -> partial s1)
    k_r1<<<160, 256>>>();
    k_route<<<gr, 256>>>(1);                  // pass 3 (s0+s1 -> c2 -> partial s2)
    k_r2_squash<<<320, 256>>>(out);           // 2560 warps covers 2560 (b,c)
}

// round 17
// speedup vs baseline: 1.0347x; 1.0347x over previous
#include <cuda_runtime.h>

// ---------------- problem constants ----------------
#define Bsz 256
#define Nn  2304
#define Cc  10
#define Dd  16
#define Oo  160          // Cc*Dd
#define Ii  8

#define K1_BT 32                 // batches per GEMM block
#define K1_NC 16                 // n per GEMM block
#define K1_CH (Nn / K1_NC)       // 144 chunks
#define K1_ST 4                  // n per W smem stage
#define K2_NC 24                 // n per routing warp
#define K2_CH (Nn / K2_NC)       // 96 chunks
#define PSTR  K1_CH              // partial-buffer chunk stride (max of 144,96)

// ---------------- scratch (static device globals; no runtime alloc) ----------
__device__ float g_uhat[(size_t)Bsz * Nn * Oo];      // 377 MB fp32
__device__ float g_P[(size_t)Bsz * PSTR * Oo];       // partial s sums
__device__ float g_s0[Bsz * Oo];
__device__ float g_s01[Bsz * Oo];

// ============ K1: 32 b / 16 n per block; vectorized LDS; W via smem =========
// 160 threads: oq = tid%40 (o-quad), grp = tid/40 -> 8 b's of 32.
// __launch_bounds__(160,3) caps regs at 136 -> 3 blocks/SM.
__global__ __launch_bounds__(160, 3) void k1_gemm(const float* __restrict__ x,
                                                  const float* __restrict__ W)
{
    __shared__ float  xs[K1_BT][K1_NC][Ii];          // 16 KB
    __shared__ float4 sW[K1_ST][Ii][Oo / 4];         // 20 KB
    const int b0    = blockIdx.x * K1_BT;
    const int n0    = blockIdx.y * K1_NC;
    const int chunk = blockIdx.y;
    const int tid   = threadIdx.x;
    const int oq    = tid % 40;                      // o = 4*oq .. 4*oq+3
    const int grp   = tid / 40;                      // 0..3 -> 8-b subgroup

    // cooperative load of x tile: [32 b][16 n][8 i] = 1024 float4
    {
        const float4* xsrc = (const float4*)x;
        for (int idx = tid; idx < K1_BT * K1_NC * Ii / 4; idx += 160) {
            int bb = idx >> 5;                       // 32 float4 per b
            int j  = idx & 31;
            ((float4*)xs)[idx] =
                xsrc[(((size_t)(b0 + bb) * Nn + n0) * Ii >> 2) + j];
        }
    }
    __syncthreads();

    float4 acc[8];
#pragma unroll
    for (int bb = 0; bb < 8; bb++) acc[bb] = make_float4(0.f, 0.f, 0.f, 0.f);

    for (int st = 0; st < K1_NC / K1_ST; st++) {
        // stage W[n0+4st .. +3]: 5120 contiguous floats = 1280 float4
        __syncthreads();                              // prev-stage reads done
        const float4* wsrc =
            (const float4*)(W + (size_t)(n0 + st * K1_ST) * Ii * Oo);
#pragma unroll
        for (int k = 0; k < (K1_ST * Ii * Oo / 4) / 160; k++)
            ((float4*)sW)[tid + k * 160] = wsrc[tid + k * 160];
        __syncthreads();

#pragma unroll
        for (int nn2 = 0; nn2 < K1_ST; nn2++) {
            const int nn = st * K1_ST + nn2;
            const int n  = n0 + nn;
            float4 w4[Ii];
#pragma unroll
            for (int i = 0; i < Ii; i++) w4[i] = sW[nn2][i][oq];   // LDS.128
#pragma unroll
            for (int bb = 0; bb < 8; bb++) {
                const int bloc = grp * 8 + bb;
                const float4 xa = *(const float4*)&xs[bloc][nn][0]; // LDS.128 bcast
                const float4 xb = *(const float4*)&xs[bloc][nn][4]; // LDS.128 bcast
                float4 u = make_float4(0.f, 0.f, 0.f, 0.f);
                u.x = fmaf(xa.x, w4[0].x, u.x); u.y = fmaf(xa.x, w4[0].y, u.y);
                u.z = fmaf(xa.x, w4[0].z, u.z); u.w = fmaf(xa.x, w4[0].w, u.w);
                u.x = fmaf(xa.y, w4[1].x, u.x); u.y = fmaf(xa.y, w4[1].y, u.y);
                u.z = fmaf(xa.y, w4[1].z, u.z); u.w = fmaf(xa.y, w4[1].w, u.w);
                u.x = fmaf(xa.z, w4[2].x, u.x); u.y = fmaf(xa.z, w4[2].y, u.y);
                u.z = fmaf(xa.z, w4[2].z, u.z); u.w = fmaf(xa.z, w4[2].w, u.w);
                u.x = fmaf(xa.w, w4[3].x, u.x); u.y = fmaf(xa.w, w4[3].y, u.y);
                u.z = fmaf(xa.w, w4[3].z, u.z); u.w = fmaf(xa.w, w4[3].w, u.w);
                u.x = fmaf(xb.x, w4[4].x, u.x); u.y = fmaf(xb.x, w4[4].y, u.y);
                u.z = fmaf(xb.x, w4[4].z, u.z); u.w = fmaf(xb.x, w4[4].w, u.w);
                u.x = fmaf(xb.y, w4[5].x, u.x); u.y = fmaf(xb.y, w4[5].y, u.y);
                u.z = fmaf(xb.y, w4[5].z, u.z); u.w = fmaf(xb.y, w4[5].w, u.w);
                u.x = fmaf(xb.z, w4[6].x, u.x); u.y = fmaf(xb.z, w4[6].y, u.y);
                u.z = fmaf(xb.z, w4[6].z, u.z); u.w = fmaf(xb.z, w4[6].w, u.w);
                u.x = fmaf(xb.w, w4[7].x, u.x); u.y = fmaf(xb.w, w4[7].y, u.y);
                u.z = fmaf(xb.w, w4[7].z, u.z); u.w = fmaf(xb.w, w4[7].w, u.w);
                *(float4*)&g_uhat[(size_t)((b0 + bloc) * Nn + n) * Oo + oq * 4] = u;
                acc[bb].x += u.x;  acc[bb].y += u.y;
                acc[bb].z += u.z;  acc[bb].w += u.w;   // fixed n-order fp32
            }
        }
    }
#pragma unroll
    for (int bb = 0; bb < 8; bb++) {
        const int bloc = grp * 8 + bb;
        *(float4*)&g_P[(size_t)((b0 + bloc) * PSTR + chunk) * Oo + oq * 4] = acc[bb];
    }
}

// ============ R0: s0 = 0.1 * sum_ch P + 0.1  (4-way chunk-split) =============
// 4 threads per (b,o): q-th thread sums chunks [36q, 36q+36); smem combine.
__global__ __launch_bounds__(256) void k_r0(void)
{
    __shared__ float sm[256];
    const int id = blockIdx.x * 256 + threadIdx.x;   // 163840 = Bsz*Oo*4
    const int q  = id & 3;
    const int bo = id >> 2;
    const int b  = bo / Oo, o = bo - b * Oo;
    const float* P = g_P + (size_t)b * PSTR * Oo + o;
    float s = 0.f;
#pragma unroll 6
    for (int ch = q * 36; ch < q * 36 + 36; ch++)
        s += P[(size_t)ch * Oo];
    sm[threadIdx.x] = s;
    __syncthreads();
    if (q == 0)
        g_s0[bo] = 0.1f * (sm[threadIdx.x] + sm[threadIdx.x + 1]
                         + sm[threadIdx.x + 2] + sm[threadIdx.x + 3]) + 0.1f;
}

// ============ routing pass: logits -> softmax -> weighted partial sums =======
__global__ __launch_bounds__(256) void k_route(int use_s01)
{
    const int lane = threadIdx.x & 31;
    const int warp = threadIdx.x >> 5;
    const int ch   = (blockIdx.x << 3) + warp;     // 0..95
    const int b    = blockIdx.y;                   // 0..255
    const int n0   = ch * K2_NC;
    const bool j2v = (lane < 16);

    const float2* sv = (const float2*)((use_s01 ? g_s01 : g_s0) + b * Oo);
    float2 sr0 = sv[lane];
    float2 sr1 = sv[lane + 32];
    float2 sr2 = make_float2(0.f, 0.f);
    if (j2v) sr2 = sv[lane + 64];

    float2 a0 = make_float2(0.f, 0.f);
    float2 a1 = make_float2(0.f, 0.f);
    float2 a2 = make_float2(0.f, 0.f);

    const float2* up = (const float2*)g_uhat
                       + ((size_t)(b * Nn + n0) * Oo >> 1) + lane;

    float2 u0 = up[0];
    float2 u1 = up[32];
    float2 u2 = make_float2(0.f, 0.f);
    if (j2v) u2 = up[64];

#pragma unroll 2
    for (int nn = 0; nn < K2_NC; nn++) {
        float2 t0, t1, t2 = make_float2(0.f, 0.f);
        if (nn + 1 < K2_NC) {
            const float2* upn = up + (Oo >> 1);
            t0 = upn[0];
            t1 = upn[32];
            if (j2v) t2 = upn[64];
        } else {
            t0 = make_float2(0.f, 0.f);
            t1 = make_float2(0.f, 0.f);
        }
        up += (Oo >> 1);

        float p0 = fmaf(u0.y, sr0.y, u0.x * sr0.x);
        float p1 = fmaf(u1.y, sr1.y, u1.x * sr1.x);
        float p2 = fmaf(u2.y, sr2.y, u2.x * sr2.x);
#pragma unroll
        for (int off = 1; off <= 4; off <<= 1) {
            p0 += __shfl_xor_sync(0xffffffffu, p0, off);
            p1 += __shfl_xor_sync(0xffffffffu, p1, off);
            p2 += __shfl_xor_sync(0xffffffffu, p2, off);
        }
        if (!j2v) p2 = -1e30f;

        float m = fmaxf(fmaxf(p0, p1), p2);
        m = fmaxf(m, __shfl_xor_sync(0xffffffffu, m, 8));
        m = fmaxf(m, __shfl_xor_sync(0xffffffffu, m, 16));

        float e0 = __expf(p0 - m);
        float e1 = __expf(p1 - m);
        float e2 = __expf(p2 - m);
        float s  = e0 + e1 + e2;
        s += __shfl_xor_sync(0xffffffffu, s, 8);
        s += __shfl_xor_sync(0xffffffffu, s, 16);
        float inv = __fdividef(1.f, s);

        float w0 = e0 * inv, w1 = e1 * inv, w2 = e2 * inv;
        a0.x = fmaf(w0, u0.x, a0.x);  a0.y = fmaf(w0, u0.y, a0.y);
        a1.x = fmaf(w1, u1.x, a1.x);  a1.y = fmaf(w1, u1.y, a1.y);
        a2.x = fmaf(w2, u2.x, a2.x);  a2.y = fmaf(w2, u2.y, a2.y);

        u0 = t0; u1 = t1; u2 = t2;
    }

    float2* P = (float2*)(g_P + (size_t)(b * PSTR + ch) * Oo);
    P[lane]      = a0;
    P[lane + 32] = a1;
    if (j2v) P[lane + 64] = a2;
}

// ============ R1: s01 = s0 + (sum_ch P + 0.1)  (4-way chunk-split) ===========
__global__ __launch_bounds__(256) void k_r1(void)
{
    __shared__ float sm[256];
    const int id = blockIdx.x * 256 + threadIdx.x;   // 163840
    const int q  = id & 3;
    const int bo = id >> 2;
    const int b  = bo / Oo, o = bo - b * Oo;
    const float* P = g_P + (size_t)b * PSTR * Oo + o;
    float s = 0.f;
#pragma unroll 6
    for (int ch = q * 24; ch < q * 24 + 24; ch++)
        s += P[(size_t)ch * Oo];
    sm[threadIdx.x] = s;
    __syncthreads();
    if (q == 0)
        g_s01[bo] = g_s0[bo] + ((sm[threadIdx.x] + sm[threadIdx.x + 1]
                               + sm[threadIdx.x + 2] + sm[threadIdx.x + 3]) + 0.1f);
}

// ============ R2: s2 = sum + 0.1 ; v = squash(s2) ============================
__global__ __launch_bounds__(256) void k_r2_squash(float* __restrict__ out)
{
    const int wg   = (blockIdx.x << 3) + (threadIdx.x >> 5);   // 2560 warps
    const int lane = threadIdx.x & 31;
    const int b = wg / Cc;
    const int c = wg - b * Cc;
    float s = 0.f;
    if (lane < Dd) {
#pragma unroll 8
        for (int ch = 0; ch < K2_CH; ch++)
            s += g_P[(size_t)(b * PSTR + ch) * Oo + c * Dd + lane];
        s += 0.1f;
    }
    float t = s * s;
#pragma unroll
    for (int off = 8; off >= 1; off >>= 1)
        t += __shfl_xor_sync(0xffffffffu, t, off);
    float nrm = sqrtf(t);
    if (lane < Dd)
        out[(b * Cc + c) * Dd + lane] = s * nrm / (1.0f + t);
}

// ============ launch =========================================================
extern "C" void kernel_launch(void* const* d_in, const int* in_sizes, int n_in,
                              void* d_out, int out_size)
{
    const float* x = (const float*)d_in[0];   // [256,2304,8]
    const float* W = (const float*)d_in[1];   // [2304,8,160]
    float* out = (float*)d_out;               // [256,10,16]

    dim3 g1(Bsz / K1_BT, K1_CH);              // 8 x 144
    dim3 gr(K2_CH / 8, Bsz);                  // 12 x 256 = 3072 blocks

    k1_gemm<<<g1, 160>>>(x, W);
    k_r0<<<640, 256>>>();                     // 4 threads per (b,o)
    k_route<<<gr, 256>>>(0);                  // pass 2 (s0 -> c1 -> partial s1)
    k_r1<<<640, 256>>>();                     // 4 threads per (b,o)
    k_route<<<gr, 256>>>(1);                  // pass 3 (s0+s1 -> c2 -> partial s2)
    k_r2_squash<<<320, 256>>>(out);
}